// round 2
// baseline (speedup 1.0000x reference)
#include <cuda_runtime.h>

#define NV 100000
#define NE 200000
#define NF 100000
#define N_EV 400000
#define N_FE 800000
#define N_FF 800000
#define WD 128

// Scratch (allocation-free rule: __device__ globals). x_f lives in d_out.
__device__ __align__(16) float g_xv[NV * WD];   // 51.2 MB
__device__ __align__(16) float g_xe[NE * WD];   // 102.4 MB
__device__ __align__(16) float g_max[NE * WD];  // 102.4 MB (reused per conv)

typedef unsigned long long u64;

__device__ __forceinline__ u64 pk2(float lo, float hi) {
    u64 r; asm("mov.b64 %0, {%1,%2};" : "=l"(r) : "f"(lo), "f"(hi)); return r;
}
__device__ __forceinline__ float2 upk2(u64 v) {
    float2 r; asm("mov.b64 {%0,%1}, %2;" : "=f"(r.x), "=f"(r.y) : "l"(v)); return r;
}
// Packed fp32x2 FMA: 2x the FFMA rate on sm_103a (PTX-only form).
__device__ __forceinline__ u64 ffma2(u64 a, u64 b, u64 c) {
    u64 d; asm("fma.rn.f32x2 %0, %1, %2, %3;" : "=l"(d) : "l"(a), "l"(b), "l"(c)); return d;
}

// ---------------- input embeddings: out = lrelu(in @ W + b) ----------------
template<int CIN>
__global__ void embed_kernel(const float* __restrict__ in, const float* __restrict__ Wt,
                             const float* __restrict__ bias, float* __restrict__ out, int n)
{
    __shared__ float sW[CIN * WD];
    __shared__ float sB[WD];
    for (int i = threadIdx.x; i < CIN * WD; i += blockDim.x) sW[i] = Wt[i];
    if (threadIdx.x < WD) sB[threadIdx.x] = bias[threadIdx.x];
    __syncthreads();
    int idx = blockIdx.x * blockDim.x + threadIdx.x;
    if (idx >= n * WD) return;
    int row = idx >> 7, j = idx & (WD - 1);
    float acc = sB[j];
#pragma unroll
    for (int k = 0; k < CIN; k++) acc = fmaf(__ldg(in + row * CIN + k), sW[k * WD + j], acc);
    out[idx] = acc > 0.f ? acc : 0.01f * acc;
}

// ---------------- fill segment-max buffer with -inf ----------------
__global__ void fill_neginf_kernel(float4* __restrict__ buf, int n4) {
    int i = blockIdx.x * blockDim.x + threadIdx.x;
    if (i < n4) {
        float ninf = __int_as_float(0xff800000);
        buf[i] = make_float4(ninf, ninf, ninf, ninf);
    }
}

// float atomic max via int/uint ordering trick (sign via bit pattern: handles -0.0)
__device__ __forceinline__ void atomicMaxF(float* addr, float v) {
    int vi = __float_as_int(v);
    if (vi >= 0) atomicMax((int*)addr, vi);
    else         atomicMin((unsigned int*)addr, (unsigned int)vi);
}

// ---------------- scatter: maxbuf[dst] = max over edges of (xdst[dst]-xsrc[src]) ----------------
// One warp per edge; each lane handles one float4 (4 channels). Pre-check load
// (monotone buffer -> stale read is safe) skips most non-improving atomics.
__global__ void scatter_max_kernel(const float* __restrict__ xsrc, const float* __restrict__ xdst,
                                   const int* __restrict__ sidx, const int* __restrict__ didx,
                                   float* __restrict__ maxbuf, int nE)
{
    int gt = blockIdx.x * blockDim.x + threadIdx.x;
    int e = gt >> 5;
    if (e >= nE) return;
    int lane = threadIdx.x & 31;
    int s = __ldg(sidx + e), d = __ldg(didx + e);
    float4 a = __ldg((const float4*)(xdst + (size_t)d * WD) + lane);
    float4 b = __ldg((const float4*)(xsrc + (size_t)s * WD) + lane);
    float* m = maxbuf + (size_t)d * WD + lane * 4;
    float4 cur = *(const float4*)m;
    float d0 = a.x - b.x, d1 = a.y - b.y, d2 = a.z - b.z, d3 = a.w - b.w;
    if (d0 > cur.x) atomicMaxF(m + 0, d0);
    if (d1 > cur.y) atomicMaxF(m + 1, d1);
    if (d2 > cur.z) atomicMaxF(m + 2, d2);
    if (d3 > cur.w) atomicMaxF(m + 3, d3);
}

// ---------------- conv GEMM: out = xdst + lrelu([xdst | fixmax] @ Wm + bm) ----------------
// Block: 256 threads, tile 64 rows x 128 cols, K=256.
// SMEM: full W (131072B) + bias (512B) + h tile 64x260 (66560B) = 198144B.
// Thread tile: 4 rows x 8 cols as 4 f32x2 accumulators; a thread owns col pairs
// {cg+16cc} (stride-16 pair ownership) so W loads are conflict-free LDS.64 of u64.
#define CONV_THREADS 256
#define TILE_R 64
#define HSTR 260
#define CONV_SMEM ((256 * WD + WD + TILE_R * HSTR) * 4)

__global__ void __launch_bounds__(CONV_THREADS, 1)
conv_kernel(const float* __restrict__ xdst, const float* __restrict__ maxbuf,
            const float* __restrict__ Wm, const float* __restrict__ bm,
            float* __restrict__ out, int n)
{
    extern __shared__ float smem[];
    float* sW = smem;              // [256][128]
    float* sB = sW + 256 * WD;     // [128]
    float* sH = sB + WD;           // [TILE_R][HSTR] : cols 0..127 = xdst, 128..255 = fixed max

    {
        float4* dstp = (float4*)sW;
        const float4* srcp = (const float4*)Wm;
        for (int i = threadIdx.x; i < 256 * WD / 4; i += CONV_THREADS) dstp[i] = __ldg(srcp + i);
        if (threadIdx.x < WD) sB[threadIdx.x] = bm[threadIdx.x];
    }

    int row0 = blockIdx.x * TILE_R;
    const float ninf = __int_as_float(0xff800000);
    for (int idx = threadIdx.x; idx < TILE_R * 256; idx += CONV_THREADS) {
        int r = idx >> 8, k = idx & 255;
        int row = row0 + r;
        float v = 0.f;
        if (row < n) {
            if (k < WD) {
                v = xdst[(size_t)row * WD + k];
            } else {
                v = maxbuf[(size_t)row * WD + (k - WD)];
                if (v == ninf) v = 0.f;   // empty segment -> 0 (reference semantics)
            }
        }
        sH[r * HSTR + k] = v;
    }
    __syncthreads();

    int rg = threadIdx.x >> 4;   // 0..15 -> rows rg*4 .. rg*4+3
    int cg = threadIdx.x & 15;   // 0..15 -> col pairs cg, cg+16, cg+32, cg+48

    const u64* sW2 = (const u64*)sW;   // [256][64] col pairs
    const u64* sB2 = (const u64*)sB;

    u64 acc[4][4];
#pragma unroll
    for (int cc = 0; cc < 4; cc++) {
        u64 b2 = sB2[cg + 16 * cc];
#pragma unroll
        for (int r = 0; r < 4; r++) acc[r][cc] = b2;
    }

    const float* hbase = sH + (rg * 4) * HSTR;
#pragma unroll 1
    for (int k = 0; k < 256; k += 4) {
        float4 h4[4];
#pragma unroll
        for (int r = 0; r < 4; r++) h4[r] = *(const float4*)(hbase + r * HSTR + k);
#pragma unroll
        for (int kk = 0; kk < 4; kk++) {
            const u64* wrow = sW2 + (k + kk) * 64 + cg;
            u64 w0 = wrow[0], w1 = wrow[16], w2 = wrow[32], w3 = wrow[48];
#pragma unroll
            for (int r = 0; r < 4; r++) {
                float hv = (kk == 0) ? h4[r].x : (kk == 1) ? h4[r].y : (kk == 2) ? h4[r].z : h4[r].w;
                u64 h2 = pk2(hv, hv);
                acc[r][0] = ffma2(h2, w0, acc[r][0]);
                acc[r][1] = ffma2(h2, w1, acc[r][1]);
                acc[r][2] = ffma2(h2, w2, acc[r][2]);
                acc[r][3] = ffma2(h2, w3, acc[r][3]);
            }
        }
    }

    // epilogue: lrelu + residual (residual read from sH xdst half; in-place safe:
    // each block only touches its own rows)
#pragma unroll
    for (int r = 0; r < 4; r++) {
        int row = row0 + rg * 4 + r;
        if (row >= n) break;
        float* orow = out + (size_t)row * WD;
        const float* hrow = sH + (rg * 4 + r) * HSTR;
#pragma unroll
        for (int cc = 0; cc < 4; cc++) {
            int c0 = 2 * (cg + 16 * cc);
            float2 v = upk2(acc[r][cc]);
            float a0 = v.x > 0.f ? v.x : 0.01f * v.x;
            float a1 = v.y > 0.f ? v.y : 0.01f * v.y;
            float2 res;
            res.x = hrow[c0] + a0;
            res.y = hrow[c0 + 1] + a1;
            *(float2*)(orow + c0) = res;
        }
    }
}

// ---------------- launch ----------------
extern "C" void kernel_launch(void* const* d_in, const int* in_sizes, int n_in,
                              void* d_out, int out_size)
{
    const float* vertices = (const float*)d_in[0];
    const float* edges    = (const float*)d_in[1];
    const float* faces    = (const float*)d_in[2];
    const int* etv_v   = (const int*)d_in[3];
    const int* etv_e   = (const int*)d_in[4];
    const int* fte_e   = (const int*)d_in[5];
    const int* fte_f   = (const int*)d_in[6];
    const int* ftf_src = (const int*)d_in[7];
    const int* ftf_dst = (const int*)d_in[8];
    const float* Wv   = (const float*)d_in[9];
    const float* bv   = (const float*)d_in[10];
    const float* We   = (const float*)d_in[11];
    const float* be   = (const float*)d_in[12];
    const float* Wf   = (const float*)d_in[13];
    const float* bf   = (const float*)d_in[14];
    const float* Wv2e = (const float*)d_in[15];
    const float* bv2e = (const float*)d_in[16];
    const float* We2f = (const float*)d_in[17];
    const float* be2f = (const float*)d_in[18];
    const float* Wm0  = (const float*)d_in[19];
    const float* bm0  = (const float*)d_in[20];
    const float* Wm1  = (const float*)d_in[21];
    const float* bm1  = (const float*)d_in[22];

    float *xv, *xe, *mx;
    cudaGetSymbolAddress((void**)&xv, g_xv);
    cudaGetSymbolAddress((void**)&xe, g_xe);
    cudaGetSymbolAddress((void**)&mx, g_max);
    float* xf = (float*)d_out;

    cudaFuncSetAttribute(conv_kernel, cudaFuncAttributeMaxDynamicSharedMemorySize, CONV_SMEM);

    // input embeddings
    embed_kernel<3><<<(NV * WD + 255) / 256, 256>>>(vertices, Wv, bv, xv, NV);
    embed_kernel<12><<<(NE * WD + 255) / 256, 256>>>(edges, We, be, xe, NE);
    embed_kernel<14><<<(NF * WD + 255) / 256, 256>>>(faces, Wf, bf, xf, NF);

    // V2E: dst = edges
    fill_neginf_kernel<<<(NE * WD / 4 + 255) / 256, 256>>>((float4*)mx, NE * WD / 4);
    scatter_max_kernel<<<(N_EV * 32 + 255) / 256, 256>>>(xv, xe, etv_v, etv_e, mx, N_EV);
    conv_kernel<<<(NE + TILE_R - 1) / TILE_R, CONV_THREADS, CONV_SMEM>>>(xe, mx, Wv2e, bv2e, xe, NE);

    // E2F: dst = faces
    fill_neginf_kernel<<<(NF * WD / 4 + 255) / 256, 256>>>((float4*)mx, NF * WD / 4);
    scatter_max_kernel<<<(N_FE * 32 + 255) / 256, 256>>>(xe, xf, fte_e, fte_f, mx, N_FE);
    conv_kernel<<<(NF + TILE_R - 1) / TILE_R, CONV_THREADS, CONV_SMEM>>>(xf, mx, We2f, be2f, xf, NF);

    // FF message layer 0
    fill_neginf_kernel<<<(NF * WD / 4 + 255) / 256, 256>>>((float4*)mx, NF * WD / 4);
    scatter_max_kernel<<<(N_FF * 32 + 255) / 256, 256>>>(xf, xf, ftf_src, ftf_dst, mx, N_FF);
    conv_kernel<<<(NF + TILE_R - 1) / TILE_R, CONV_THREADS, CONV_SMEM>>>(xf, mx, Wm0, bm0, xf, NF);

    // FF message layer 1
    fill_neginf_kernel<<<(NF * WD / 4 + 255) / 256, 256>>>((float4*)mx, NF * WD / 4);
    scatter_max_kernel<<<(N_FF * 32 + 255) / 256, 256>>>(xf, xf, ftf_src, ftf_dst, mx, N_FF);
    conv_kernel<<<(NF + TILE_R - 1) / TILE_R, CONV_THREADS, CONV_SMEM>>>(xf, mx, Wm1, bm1, xf, NF);
}

// round 3
// speedup vs baseline: 1.1316x; 1.1316x over previous
#include <cuda_runtime.h>

#define NV 100000
#define NE 200000
#define NF 100000
#define N_EV 400000
#define N_FE 800000
#define N_FF 800000
#define WD 128

// Scratch (allocation-free rule: __device__ globals). x_f lives in d_out.
__device__ __align__(16) float g_xv[NV * WD];   // 51.2 MB
__device__ __align__(16) float g_xe[NE * WD];   // 102.4 MB
__device__ __align__(16) float g_max[NE * WD];  // 102.4 MB (per-conv "maxes")
__device__ int g_cnt[NE];        // per-dst degree
__device__ int g_ptr[NE];        // CSR row offsets (exclusive scan)
__device__ int g_cur[NE];        // fill cursors
__device__ int g_bsum[1024];     // scan block sums
__device__ int g_csr[N_FE];      // CSR column (src) indices, max 800k

typedef unsigned long long u64;

__device__ __forceinline__ u64 pk2(float lo, float hi) {
    u64 r; asm("mov.b64 %0, {%1,%2};" : "=l"(r) : "f"(lo), "f"(hi)); return r;
}
__device__ __forceinline__ float2 upk2(u64 v) {
    float2 r; asm("mov.b64 {%0,%1}, %2;" : "=f"(r.x), "=f"(r.y) : "l"(v)); return r;
}
// Packed fp32x2 FMA: 2x the FFMA rate on sm_103a (PTX-only form).
__device__ __forceinline__ u64 ffma2(u64 a, u64 b, u64 c) {
    u64 d; asm("fma.rn.f32x2 %0, %1, %2, %3;" : "=l"(d) : "l"(a), "l"(b), "l"(c)); return d;
}

// ---------------- input embeddings: out = lrelu(in @ W + b) ----------------
template<int CIN>
__global__ void embed_kernel(const float* __restrict__ in, const float* __restrict__ Wt,
                             const float* __restrict__ bias, float* __restrict__ out, int n)
{
    __shared__ float sW[CIN * WD];
    __shared__ float sB[WD];
    for (int i = threadIdx.x; i < CIN * WD; i += blockDim.x) sW[i] = Wt[i];
    if (threadIdx.x < WD) sB[threadIdx.x] = bias[threadIdx.x];
    __syncthreads();
    int idx = blockIdx.x * blockDim.x + threadIdx.x;
    if (idx >= n * WD) return;
    int row = idx >> 7, j = idx & (WD - 1);
    float acc = sB[j];
#pragma unroll
    for (int k = 0; k < CIN; k++) acc = fmaf(__ldg(in + row * CIN + k), sW[k * WD + j], acc);
    out[idx] = acc > 0.f ? acc : 0.01f * acc;
}

// ---------------- CSR build: histogram -> scan -> fill ----------------
__global__ void zero_kernel(int* __restrict__ p, int n) {
    int i = blockIdx.x * blockDim.x + threadIdx.x;
    if (i < n) p[i] = 0;
}

__global__ void hist_kernel(const int* __restrict__ didx, int* __restrict__ cnt, int nE) {
    int e = blockIdx.x * blockDim.x + threadIdx.x;
    if (e < nE) atomicAdd(&cnt[__ldg(didx + e)], 1);
}

// per-block exclusive scan (256/block) + block sums
__global__ void scan1_kernel(const int* __restrict__ cnt, int* __restrict__ excl,
                             int* __restrict__ bsum, int n)
{
    __shared__ int s[256];
    int i = blockIdx.x * 256 + threadIdx.x;
    int v = (i < n) ? cnt[i] : 0;
    s[threadIdx.x] = v; __syncthreads();
    for (int off = 1; off < 256; off <<= 1) {
        int t = (threadIdx.x >= (unsigned)off) ? s[threadIdx.x - off] : 0;
        __syncthreads();
        s[threadIdx.x] += t;
        __syncthreads();
    }
    if (i < n) excl[i] = s[threadIdx.x] - v;
    if (threadIdx.x == 255) bsum[blockIdx.x] = s[255];
}

// single-block exclusive scan of block sums (nb <= 1024)
__global__ void scan2_kernel(int* __restrict__ bsum, int nb) {
    __shared__ int s[1024];
    int v = ((int)threadIdx.x < nb) ? bsum[threadIdx.x] : 0;
    s[threadIdx.x] = v; __syncthreads();
    for (int off = 1; off < 1024; off <<= 1) {
        int t = (threadIdx.x >= (unsigned)off) ? s[threadIdx.x - off] : 0;
        __syncthreads();
        s[threadIdx.x] += t;
        __syncthreads();
    }
    if ((int)threadIdx.x < nb) bsum[threadIdx.x] = s[threadIdx.x] - v;
}

__global__ void scan3_kernel(int* __restrict__ ptr, const int* __restrict__ bsum,
                             int* __restrict__ cur, int n)
{
    int i = blockIdx.x * blockDim.x + threadIdx.x;
    if (i < n) {
        int p = ptr[i] + bsum[i >> 8];
        ptr[i] = p;
        cur[i] = p;
    }
}

__global__ void fill_csr_kernel(const int* __restrict__ sidx, const int* __restrict__ didx,
                                int* __restrict__ cur, int* __restrict__ csr, int nE)
{
    int e = blockIdx.x * blockDim.x + threadIdx.x;
    if (e < nE) {
        int d = __ldg(didx + e);
        int pos = atomicAdd(&cur[d], 1);
        csr[pos] = __ldg(sidx + e);
    }
}

// ---------------- segment min -> maxes ----------------
// max_e(xdst[d] - xsrc[s_e]) == xdst[d] - min_e(xsrc[s_e])  (fp-monotone, exact)
// One warp per dst row; lane owns one float4 (4 channels). No atomics.
__global__ void segmin_kernel(const float* __restrict__ xsrc, const float* __restrict__ xdst,
                              const int* __restrict__ ptr, const int* __restrict__ cnt,
                              const int* __restrict__ csr, float* __restrict__ out, int ndst)
{
    int w = (blockIdx.x * blockDim.x + threadIdx.x) >> 5;
    if (w >= ndst) return;
    int lane = threadIdx.x & 31;
    int deg = __ldg(cnt + w);
    int base = __ldg(ptr + w);
    const float inf = __int_as_float(0x7f800000);
    float4 mn = make_float4(inf, inf, inf, inf);
    for (int i = 0; i < deg; i++) {
        int s = __ldg(csr + base + i);
        float4 v = __ldg((const float4*)(xsrc + (size_t)s * WD) + lane);
        mn.x = fminf(mn.x, v.x); mn.y = fminf(mn.y, v.y);
        mn.z = fminf(mn.z, v.z); mn.w = fminf(mn.w, v.w);
    }
    float4 o;
    if (deg > 0) {
        float4 a = __ldg((const float4*)(xdst + (size_t)w * WD) + lane);
        o = make_float4(a.x - mn.x, a.y - mn.y, a.z - mn.z, a.w - mn.w);
    } else {
        o = make_float4(0.f, 0.f, 0.f, 0.f);
    }
    ((float4*)(out + (size_t)w * WD))[lane] = o;
}

// ---------------- conv GEMM: out = xdst + lrelu([xdst | maxes] @ Wm + bm) ----------------
#define CONV_THREADS 256
#define TILE_R 64
#define HSTR 260
#define CONV_SMEM ((256 * WD + WD + TILE_R * HSTR) * 4)

__global__ void __launch_bounds__(CONV_THREADS, 1)
conv_kernel(const float* __restrict__ xdst, const float* __restrict__ maxbuf,
            const float* __restrict__ Wm, const float* __restrict__ bm,
            float* __restrict__ out, int n)
{
    extern __shared__ float smem[];
    float* sW = smem;              // [256][128]
    float* sB = sW + 256 * WD;     // [128]
    float* sH = sB + WD;           // [TILE_R][HSTR] : cols 0..127 = xdst, 128..255 = maxes

    {
        float4* dstp = (float4*)sW;
        const float4* srcp = (const float4*)Wm;
        for (int i = threadIdx.x; i < 256 * WD / 4; i += CONV_THREADS) dstp[i] = __ldg(srcp + i);
        if (threadIdx.x < WD) sB[threadIdx.x] = bm[threadIdx.x];
    }

    int row0 = blockIdx.x * TILE_R;
    for (int idx = threadIdx.x; idx < TILE_R * 256; idx += CONV_THREADS) {
        int r = idx >> 8, k = idx & 255;
        int row = row0 + r;
        float v = 0.f;
        if (row < n) {
            if (k < WD) v = xdst[(size_t)row * WD + k];
            else        v = maxbuf[(size_t)row * WD + (k - WD)];
        }
        sH[r * HSTR + k] = v;
    }
    __syncthreads();

    int rg = threadIdx.x >> 4;   // 0..15 -> rows rg*4 .. rg*4+3
    int cg = threadIdx.x & 15;   // 0..15 -> col pairs cg, cg+16, cg+32, cg+48

    const u64* sW2 = (const u64*)sW;   // [256][64] col pairs
    const u64* sB2 = (const u64*)sB;

    u64 acc[4][4];
#pragma unroll
    for (int cc = 0; cc < 4; cc++) {
        u64 b2 = sB2[cg + 16 * cc];
#pragma unroll
        for (int r = 0; r < 4; r++) acc[r][cc] = b2;
    }

    const float* hbase = sH + (rg * 4) * HSTR;
#pragma unroll 1
    for (int k = 0; k < 256; k += 4) {
        float4 h4[4];
#pragma unroll
        for (int r = 0; r < 4; r++) h4[r] = *(const float4*)(hbase + r * HSTR + k);
#pragma unroll
        for (int kk = 0; kk < 4; kk++) {
            const u64* wrow = sW2 + (k + kk) * 64 + cg;
            u64 w0 = wrow[0], w1 = wrow[16], w2 = wrow[32], w3 = wrow[48];
#pragma unroll
            for (int r = 0; r < 4; r++) {
                float hv = (kk == 0) ? h4[r].x : (kk == 1) ? h4[r].y : (kk == 2) ? h4[r].z : h4[r].w;
                u64 h2 = pk2(hv, hv);
                acc[r][0] = ffma2(h2, w0, acc[r][0]);
                acc[r][1] = ffma2(h2, w1, acc[r][1]);
                acc[r][2] = ffma2(h2, w2, acc[r][2]);
                acc[r][3] = ffma2(h2, w3, acc[r][3]);
            }
        }
    }

    // epilogue: lrelu + residual (residual read from sH xdst half; in-place safe)
#pragma unroll
    for (int r = 0; r < 4; r++) {
        int row = row0 + rg * 4 + r;
        if (row >= n) break;
        float* orow = out + (size_t)row * WD;
        const float* hrow = sH + (rg * 4 + r) * HSTR;
#pragma unroll
        for (int cc = 0; cc < 4; cc++) {
            int c0 = 2 * (cg + 16 * cc);
            float2 v = upk2(acc[r][cc]);
            float a0 = v.x > 0.f ? v.x : 0.01f * v.x;
            float a1 = v.y > 0.f ? v.y : 0.01f * v.y;
            float2 res;
            res.x = hrow[c0] + a0;
            res.y = hrow[c0 + 1] + a1;
            *(float2*)(orow + c0) = res;
        }
    }
}

// ---------------- host-side helpers ----------------
static void build_csr_and_min(const float* xsrc, const float* xdst,
                              const int* sidx, const int* didx,
                              int nE, int ndst,
                              int* cnt, int* ptr, int* cur, int* bsum, int* csr,
                              float* mx)
{
    int nb = (ndst + 255) / 256;
    zero_kernel<<<(ndst + 1023) / 1024, 1024>>>(cnt, ndst);
    hist_kernel<<<(nE + 255) / 256, 256>>>(didx, cnt, nE);
    scan1_kernel<<<nb, 256>>>(cnt, ptr, bsum, ndst);
    scan2_kernel<<<1, 1024>>>(bsum, nb);
    scan3_kernel<<<(ndst + 255) / 256, 256>>>(ptr, bsum, cur, ndst);
    fill_csr_kernel<<<(nE + 255) / 256, 256>>>(sidx, didx, cur, csr, nE);
    segmin_kernel<<<(ndst + 7) / 8, 256>>>(xsrc, xdst, ptr, cnt, csr, mx, ndst);
}

extern "C" void kernel_launch(void* const* d_in, const int* in_sizes, int n_in,
                              void* d_out, int out_size)
{
    const float* vertices = (const float*)d_in[0];
    const float* edges    = (const float*)d_in[1];
    const float* faces    = (const float*)d_in[2];
    const int* etv_v   = (const int*)d_in[3];
    const int* etv_e   = (const int*)d_in[4];
    const int* fte_e   = (const int*)d_in[5];
    const int* fte_f   = (const int*)d_in[6];
    const int* ftf_src = (const int*)d_in[7];
    const int* ftf_dst = (const int*)d_in[8];
    const float* Wv   = (const float*)d_in[9];
    const float* bv   = (const float*)d_in[10];
    const float* We   = (const float*)d_in[11];
    const float* be   = (const float*)d_in[12];
    const float* Wf   = (const float*)d_in[13];
    const float* bf   = (const float*)d_in[14];
    const float* Wv2e = (const float*)d_in[15];
    const float* bv2e = (const float*)d_in[16];
    const float* We2f = (const float*)d_in[17];
    const float* be2f = (const float*)d_in[18];
    const float* Wm0  = (const float*)d_in[19];
    const float* bm0  = (const float*)d_in[20];
    const float* Wm1  = (const float*)d_in[21];
    const float* bm1  = (const float*)d_in[22];

    float *xv, *xe, *mx;
    int *cnt, *ptr, *cur, *bsum, *csr;
    cudaGetSymbolAddress((void**)&xv, g_xv);
    cudaGetSymbolAddress((void**)&xe, g_xe);
    cudaGetSymbolAddress((void**)&mx, g_max);
    cudaGetSymbolAddress((void**)&cnt, g_cnt);
    cudaGetSymbolAddress((void**)&ptr, g_ptr);
    cudaGetSymbolAddress((void**)&cur, g_cur);
    cudaGetSymbolAddress((void**)&bsum, g_bsum);
    cudaGetSymbolAddress((void**)&csr, g_csr);
    float* xf = (float*)d_out;

    cudaFuncSetAttribute(conv_kernel, cudaFuncAttributeMaxDynamicSharedMemorySize, CONV_SMEM);

    // input embeddings
    embed_kernel<3><<<(NV * WD + 255) / 256, 256>>>(vertices, Wv, bv, xv, NV);
    embed_kernel<12><<<(NE * WD + 255) / 256, 256>>>(edges, We, be, xe, NE);
    embed_kernel<14><<<(NF * WD + 255) / 256, 256>>>(faces, Wf, bf, xf, NF);

    // V2E: dst = edges
    build_csr_and_min(xv, xe, etv_v, etv_e, N_EV, NE, cnt, ptr, cur, bsum, csr, mx);
    conv_kernel<<<(NE + TILE_R - 1) / TILE_R, CONV_THREADS, CONV_SMEM>>>(xe, mx, Wv2e, bv2e, xe, NE);

    // E2F: dst = faces
    build_csr_and_min(xe, xf, fte_e, fte_f, N_FE, NF, cnt, ptr, cur, bsum, csr, mx);
    conv_kernel<<<(NF + TILE_R - 1) / TILE_R, CONV_THREADS, CONV_SMEM>>>(xf, mx, We2f, be2f, xf, NF);

    // FF message layer 0
    build_csr_and_min(xf, xf, ftf_src, ftf_dst, N_FF, NF, cnt, ptr, cur, bsum, csr, mx);
    conv_kernel<<<(NF + TILE_R - 1) / TILE_R, CONV_THREADS, CONV_SMEM>>>(xf, mx, Wm0, bm0, xf, NF);

    // FF message layer 1
    build_csr_and_min(xf, xf, ftf_src, ftf_dst, N_FF, NF, cnt, ptr, cur, bsum, csr, mx);
    conv_kernel<<<(NF + TILE_R - 1) / TILE_R, CONV_THREADS, CONV_SMEM>>>(xf, mx, Wm1, bm1, xf, NF);
}

// round 5
// speedup vs baseline: 2.4304x; 2.1477x over previous
#include <cuda_runtime.h>

#define NV 100000
#define NE 200000
#define NF 100000
#define N_EV 400000
#define N_FE 800000
#define N_FF 800000
#define WD 128
#define NDST_TOT (NE + NF + NF)          // 400000 combined dst slots
#define NEDGE_TOT (N_EV + N_FE + N_FF)   // 2,000,000 combined edges

// Scratch (allocation-free rule: __device__ globals). x_f lives in d_out.
__device__ __align__(16) float g_xv[NV * WD];
__device__ __align__(16) float g_xe[NE * WD];
__device__ __align__(16) float g_max[NE * WD];
__device__ int g_cnt[NDST_TOT];
__device__ int g_ptr[NDST_TOT];
__device__ int g_cur[NDST_TOT];
__device__ int g_bsum[256];
__device__ int g_csr[NEDGE_TOT];
__device__ unsigned g_barcnt;
__device__ volatile unsigned g_bargen;

typedef unsigned long long u64;

__device__ __forceinline__ u64 pk2(float lo, float hi) {
    u64 r; asm("mov.b64 %0, {%1,%2};" : "=l"(r) : "f"(lo), "f"(hi)); return r;
}
__device__ __forceinline__ float2 upk2(u64 v) {
    float2 r; asm("mov.b64 {%0,%1}, %2;" : "=f"(r.x), "=f"(r.y) : "l"(v)); return r;
}
// Packed fp32x2 FMA: 2x the FFMA rate on sm_103a (PTX-only form).
__device__ __forceinline__ u64 ffma2(u64 a, u64 b, u64 c) {
    u64 d; asm("fma.rn.f32x2 %0, %1, %2, %3;" : "=l"(d) : "l"(a), "l"(b), "l"(c)); return d;
}
__device__ __forceinline__ void cp16(unsigned dst, const void* src, int srcsz) {
    asm volatile("cp.async.cg.shared.global [%0], [%1], 16, %2;"
                 :: "r"(dst), "l"(src), "r"(srcsz));
}
#define CP_COMMIT() asm volatile("cp.async.commit_group;")
#define CP_WAIT1()  asm volatile("cp.async.wait_group 1;")
#define CP_WAIT0()  asm volatile("cp.async.wait_group 0;")

// ---------------- software global barrier (all blocks co-resident) ----------------
__device__ __forceinline__ void gbar() {
    __syncthreads();
    if (threadIdx.x == 0) {
        unsigned gen = g_bargen;
        __threadfence();
        if (atomicAdd(&g_barcnt, 1) == gridDim.x - 1) {
            g_barcnt = 0;
            __threadfence();
            g_bargen = gen + 1;
        } else {
            while (g_bargen == gen) __nanosleep(64);
        }
        __threadfence();
    }
    __syncthreads();
}

// inclusive block scan (1024 threads), returns inclusive val; *tot = block total
__device__ __forceinline__ int block_scan_incl(int v, int* tot, int* swarp) {
    int lane = threadIdx.x & 31, wid = threadIdx.x >> 5;
    int s = v;
#pragma unroll
    for (int o = 1; o < 32; o <<= 1) { int t = __shfl_up_sync(~0u, s, o); if (lane >= o) s += t; }
    if (lane == 31) swarp[wid] = s;
    __syncthreads();
    if (wid == 0) {
        int w = swarp[lane];
#pragma unroll
        for (int o = 1; o < 32; o <<= 1) { int t = __shfl_up_sync(~0u, w, o); if (lane >= o) w += t; }
        swarp[lane] = w;
    }
    __syncthreads();
    int add = (wid > 0) ? swarp[wid - 1] : 0;
    *tot = swarp[31];
    int r = s + add;
    __syncthreads();
    return r;
}

// ---------------- build all 3 CSRs in ONE kernel ----------------
__global__ void __launch_bounds__(1024)
build_csr_all(const int* __restrict__ etv_v, const int* __restrict__ etv_e,
              const int* __restrict__ fte_e, const int* __restrict__ fte_f,
              const int* __restrict__ ftf_src, const int* __restrict__ ftf_dst)
{
    __shared__ int swarp[32];
    int gtid = blockIdx.x * 1024 + threadIdx.x;
    int gstride = gridDim.x * 1024;

    // zero counts
    for (int i = gtid; i < NDST_TOT; i += gstride) g_cnt[i] = 0;
    gbar();
    // histogram all 3 graphs
    for (int e = gtid; e < N_EV; e += gstride) atomicAdd(&g_cnt[__ldg(etv_e + e)], 1);
    for (int e = gtid; e < N_FE; e += gstride) atomicAdd(&g_cnt[NE + __ldg(fte_f + e)], 1);
    for (int e = gtid; e < N_FF; e += gstride) atomicAdd(&g_cnt[NE + NF + __ldg(ftf_dst + e)], 1);
    gbar();
    // exclusive scan over combined counts
    const int CHUNK = (NDST_TOT + gridDim.x - 1) / gridDim.x;
    int base = blockIdx.x * CHUNK;
    int lim = min(base + CHUNK, NDST_TOT);
    int carry = 0;
    for (int t = base; t < base + CHUNK; t += 1024) {
        int i = t + threadIdx.x;
        int v = (i < lim) ? g_cnt[i] : 0;
        int tot; int incl = block_scan_incl(v, &tot, swarp);
        if (i < lim) g_ptr[i] = carry + incl - v;
        carry += tot;
    }
    if (threadIdx.x == 0) g_bsum[blockIdx.x] = carry;
    gbar();
    if (blockIdx.x == 0) {
        int v = ((int)threadIdx.x < (int)gridDim.x) ? g_bsum[threadIdx.x] : 0;
        int tot; int incl = block_scan_incl(v, &tot, swarp);
        if ((int)threadIdx.x < (int)gridDim.x) g_bsum[threadIdx.x] = incl - v;
    }
    gbar();
    {
        int off = g_bsum[blockIdx.x];
        for (int i = base + threadIdx.x; i < lim; i += 1024) {
            int p = g_ptr[i] + off; g_ptr[i] = p; g_cur[i] = p;
        }
    }
    gbar();
    // fill CSR (order within a segment is irrelevant: consumer is min-reduce)
    for (int e = gtid; e < N_EV; e += gstride) {
        int d = __ldg(etv_e + e);
        g_csr[atomicAdd(&g_cur[d], 1)] = __ldg(etv_v + e);
    }
    for (int e = gtid; e < N_FE; e += gstride) {
        int d = NE + __ldg(fte_f + e);
        g_csr[atomicAdd(&g_cur[d], 1)] = __ldg(fte_e + e);
    }
    for (int e = gtid; e < N_FF; e += gstride) {
        int d = NE + NF + __ldg(ftf_dst + e);
        g_csr[atomicAdd(&g_cur[d], 1)] = __ldg(ftf_src + e);
    }
}

// ---------------- input embeddings: out = lrelu(in @ W + b) ----------------
template<int CIN>
__global__ void embed_kernel(const float* __restrict__ in, const float* __restrict__ Wt,
                             const float* __restrict__ bias, float* __restrict__ out, int n)
{
    __shared__ float sW[CIN * WD];
    __shared__ float sB[WD];
    for (int i = threadIdx.x; i < CIN * WD; i += blockDim.x) sW[i] = Wt[i];
    if (threadIdx.x < WD) sB[threadIdx.x] = bias[threadIdx.x];
    __syncthreads();
    int idx = blockIdx.x * blockDim.x + threadIdx.x;
    if (idx >= n * WD) return;
    int row = idx >> 7, j = idx & (WD - 1);
    float acc = sB[j];
#pragma unroll
    for (int k = 0; k < CIN; k++) acc = fmaf(__ldg(in + row * CIN + k), sW[k * WD + j], acc);
    out[idx] = acc > 0.f ? acc : 0.01f * acc;
}

// ---------------- segment min -> maxes ----------------
// max_e(xdst[d] - xsrc[s_e]) == xdst[d] - min_e(xsrc[s_e])  (fp-monotone, exact)
__global__ void segmin_kernel(const float* __restrict__ xsrc, const float* __restrict__ xdst,
                              const int* __restrict__ ptr, const int* __restrict__ cnt,
                              const int* __restrict__ csr, float* __restrict__ out, int ndst)
{
    int w = (blockIdx.x * blockDim.x + threadIdx.x) >> 5;
    if (w >= ndst) return;
    int lane = threadIdx.x & 31;
    int deg = __ldg(cnt + w);
    int base = __ldg(ptr + w);
    const float inf = __int_as_float(0x7f800000);
    float4 mn = make_float4(inf, inf, inf, inf);
    int i = 0;
    for (; i + 2 <= deg; i += 2) {
        int s0 = __ldg(csr + base + i), s1 = __ldg(csr + base + i + 1);
        float4 v0 = __ldg((const float4*)(xsrc + (size_t)s0 * WD) + lane);
        float4 v1 = __ldg((const float4*)(xsrc + (size_t)s1 * WD) + lane);
        mn.x = fminf(mn.x, fminf(v0.x, v1.x)); mn.y = fminf(mn.y, fminf(v0.y, v1.y));
        mn.z = fminf(mn.z, fminf(v0.z, v1.z)); mn.w = fminf(mn.w, fminf(v0.w, v1.w));
    }
    if (i < deg) {
        int s = __ldg(csr + base + i);
        float4 v = __ldg((const float4*)(xsrc + (size_t)s * WD) + lane);
        mn.x = fminf(mn.x, v.x); mn.y = fminf(mn.y, v.y);
        mn.z = fminf(mn.z, v.z); mn.w = fminf(mn.w, v.w);
    }
    float4 o;
    if (deg > 0) {
        float4 a = __ldg((const float4*)(xdst + (size_t)w * WD) + lane);
        o = make_float4(a.x - mn.x, a.y - mn.y, a.z - mn.z, a.w - mn.w);
    } else {
        o = make_float4(0.f, 0.f, 0.f, 0.f);
    }
    ((float4*)(out + (size_t)w * WD))[lane] = o;
}

// ---------------- conv GEMM: out = xdst + lrelu([xdst | maxes] @ Wm + bm) ----------------
// 256 threads, tile 128 rows x 128 cols, K=256 streamed as 4 x 64 chunks,
// double-buffered cp.async. Thread tile: 4 rows x 16 cols (8 f32x2 accs/row).
#define CONV_THREADS 256
#define TILE_R 128
#define KC 64
#define HSTR 68
#define CONV_SMEM ((256 * WD + WD + 2 * TILE_R * HSTR) * 4)   // 201216 B

__global__ void __launch_bounds__(CONV_THREADS, 1)
conv_kernel(const float* __restrict__ xdst, const float* __restrict__ maxbuf,
            const float* __restrict__ Wm, const float* __restrict__ bm,
            float* __restrict__ out, int n)
{
    extern __shared__ float smem[];
    float* sW = smem;                  // [256][128]
    float* sB = sW + 256 * WD;         // [128]
    float* sH = sB + WD;               // [2][TILE_R][HSTR]

    int tid = threadIdx.x;
    int row0 = blockIdx.x * TILE_R;
    int rg = tid >> 3;                 // 0..31 -> rows rg*4..rg*4+3
    int cgp = tid & 7;                 // col pairs cgp + 8*cc, cc=0..7

    unsigned sWa = (unsigned)__cvta_generic_to_shared(sW);
    unsigned sHa = (unsigned)__cvta_generic_to_shared(sH);

    // prologue: async-load W + h chunk 0 (group 0)
    {
        const char* wsrc = (const char*)Wm;
#pragma unroll 4
        for (int t = 0; t < 32; t++) {
            int w = tid + t * 256;
            cp16(sWa + w * 16, wsrc + w * 16, 16);
        }
    }
    // h chunk loader: chunk c covers k [c*64, c*64+64); c<2 from xdst, else maxbuf
    // 2048 16B words per chunk, 8 per thread
    {
        const char* src = (const char*)xdst;
#pragma unroll
        for (int t = 0; t < 8; t++) {
            int idx = tid + t * 256;
            int row = idx >> 4, w = idx & 15;
            int sz = (row0 + row < n) ? 16 : 0;
            cp16(sHa + (row * HSTR) * 4 + w * 16,
                 src + (size_t)(row0 + row) * 512 + w * 16, sz);
        }
    }
    CP_COMMIT();
    if (tid < WD) sB[tid] = bm[tid];

    const u64* sW2 = (const u64*)sW;
    u64 acc[4][8];

#pragma unroll 1
    for (int c = 0; c < 4; c++) {
        if (c + 1 < 4) {   // prefetch chunk c+1 into buf (c+1)&1
            int cn = c + 1;
            const char* src = (const char*)((cn < 2) ? xdst : maxbuf);
            int cboff = (cn & 1) * 256;
            unsigned hb = sHa + ((cn & 1) * TILE_R * HSTR) * 4;
#pragma unroll
            for (int t = 0; t < 8; t++) {
                int idx = tid + t * 256;
                int row = idx >> 4, w = idx & 15;
                int sz = (row0 + row < n) ? 16 : 0;
                cp16(hb + (row * HSTR) * 4 + w * 16,
                     src + (size_t)(row0 + row) * 512 + cboff + w * 16, sz);
            }
            CP_COMMIT();
            CP_WAIT1();
        } else {
            CP_WAIT0();
        }
        __syncthreads();

        if (c == 0) {
            const u64* sB2 = (const u64*)sB;
#pragma unroll
            for (int cc = 0; cc < 8; cc++) {
                u64 b2 = sB2[cgp + 8 * cc];
#pragma unroll
                for (int r = 0; r < 4; r++) acc[r][cc] = b2;
            }
        }

        const float* hb = sH + (c & 1) * TILE_R * HSTR + (rg * 4) * HSTR;
        int kbase = c * KC;
#pragma unroll 1
        for (int k4 = 0; k4 < KC / 4; k4++) {
            float4 h4[4];
#pragma unroll
            for (int r = 0; r < 4; r++) h4[r] = *(const float4*)(hb + r * HSTR + k4 * 4);
#pragma unroll
            for (int kk = 0; kk < 4; kk++) {
                const u64* wr = sW2 + (size_t)(kbase + k4 * 4 + kk) * 64 + cgp;
                u64 w[8];
#pragma unroll
                for (int cc = 0; cc < 8; cc++) w[cc] = wr[8 * cc];
#pragma unroll
                for (int r = 0; r < 4; r++) {
                    float hv = (kk == 0) ? h4[r].x : (kk == 1) ? h4[r].y
                             : (kk == 2) ? h4[r].z : h4[r].w;
                    u64 h2 = pk2(hv, hv);
#pragma unroll
                    for (int cc = 0; cc < 8; cc++) acc[r][cc] = ffma2(h2, w[cc], acc[r][cc]);
                }
            }
        }
        __syncthreads();
    }

    // epilogue: lrelu into smem stage, then coalesced residual+store
    float* sO = sH;   // [TILE_R][132], 16896 floats <= 17408 available
#pragma unroll
    for (int r = 0; r < 4; r++) {
        int lrow = rg * 4 + r;
#pragma unroll
        for (int cc = 0; cc < 8; cc++) {
            float2 v = upk2(acc[r][cc]);
            float2 a;
            a.x = v.x > 0.f ? v.x : 0.01f * v.x;
            a.y = v.y > 0.f ? v.y : 0.01f * v.y;
            *(float2*)(sO + lrow * 132 + 2 * (cgp + 8 * cc)) = a;
        }
    }
    __syncthreads();
#pragma unroll 1
    for (int idx = tid; idx < TILE_R * 32; idx += CONV_THREADS) {
        int row = idx >> 5, c4 = idx & 31;
        int grow = row0 + row;
        if (grow < n) {
            float4 o = *(const float4*)(sO + row * 132 + c4 * 4);
            float4 x = __ldg((const float4*)(xdst + (size_t)grow * WD) + c4);
            float4 res = make_float4(x.x + o.x, x.y + o.y, x.z + o.z, x.w + o.w);
            *((float4*)(out + (size_t)grow * WD) + c4) = res;
        }
    }
}

// ---------------- launch ----------------
extern "C" void kernel_launch(void* const* d_in, const int* in_sizes, int n_in,
                              void* d_out, int out_size)
{
    const float* vertices = (const float*)d_in[0];
    const float* edges    = (const float*)d_in[1];
    const float* faces    = (const float*)d_in[2];
    const int* etv_v   = (const int*)d_in[3];
    const int* etv_e   = (const int*)d_in[4];
    const int* fte_e   = (const int*)d_in[5];
    const int* fte_f   = (const int*)d_in[6];
    const int* ftf_src = (const int*)d_in[7];
    const int* ftf_dst = (const int*)d_in[8];
    const float* Wv   = (const float*)d_in[9];
    const float* bv   = (const float*)d_in[10];
    const float* We   = (const float*)d_in[11];
    const float* be   = (const float*)d_in[12];
    const float* Wf   = (const float*)d_in[13];
    const float* bf   = (const float*)d_in[14];
    const float* Wv2e = (const float*)d_in[15];
    const float* bv2e = (const float*)d_in[16];
    const float* We2f = (const float*)d_in[17];
    const float* be2f = (const float*)d_in[18];
    const float* Wm0  = (const float*)d_in[19];
    const float* bm0  = (const float*)d_in[20];
    const float* Wm1  = (const float*)d_in[21];
    const float* bm1  = (const float*)d_in[22];

    float *xv, *xe, *mx;
    int *cnt, *ptr, *csr;
    cudaGetSymbolAddress((void**)&xv, g_xv);
    cudaGetSymbolAddress((void**)&xe, g_xe);
    cudaGetSymbolAddress((void**)&mx, g_max);
    cudaGetSymbolAddress((void**)&cnt, g_cnt);
    cudaGetSymbolAddress((void**)&ptr, g_ptr);
    cudaGetSymbolAddress((void**)&csr, g_csr);
    float* xf = (float*)d_out;

    cudaFuncSetAttribute(conv_kernel, cudaFuncAttributeMaxDynamicSharedMemorySize, CONV_SMEM);

    // launch 0: all 3 CSRs (index-only; independent of features)
    build_csr_all<<<148, 1024>>>(etv_v, etv_e, fte_e, fte_f, ftf_src, ftf_dst);

    // launches 1-3: embeddings
    embed_kernel<3><<<(NV * WD + 255) / 256, 256>>>(vertices, Wv, bv, xv, NV);
    embed_kernel<12><<<(NE * WD + 255) / 256, 256>>>(edges, We, be, xe, NE);
    embed_kernel<14><<<(NF * WD + 255) / 256, 256>>>(faces, Wf, bf, xf, NF);

    // V2E (launches 4,5 — conv1 is the ncu-profiled launch)
    segmin_kernel<<<(NE + 7) / 8, 256>>>(xv, xe, ptr, cnt, csr, mx, NE);
    conv_kernel<<<(NE + TILE_R - 1) / TILE_R, CONV_THREADS, CONV_SMEM>>>(xe, mx, Wv2e, bv2e, xe, NE);

    // E2F
    segmin_kernel<<<(NF + 7) / 8, 256>>>(xe, xf, ptr + NE, cnt + NE, csr, mx, NF);
    conv_kernel<<<(NF + TILE_R - 1) / TILE_R, CONV_THREADS, CONV_SMEM>>>(xf, mx, We2f, be2f, xf, NF);

    // FF message layer 0 (ftf CSR reused)
    segmin_kernel<<<(NF + 7) / 8, 256>>>(xf, xf, ptr + NE + NF, cnt + NE + NF, csr, mx, NF);
    conv_kernel<<<(NF + TILE_R - 1) / TILE_R, CONV_THREADS, CONV_SMEM>>>(xf, mx, Wm0, bm0, xf, NF);

    // FF message layer 1
    segmin_kernel<<<(NF + 7) / 8, 256>>>(xf, xf, ptr + NE + NF, cnt + NE + NF, csr, mx, NF);
    conv_kernel<<<(NF + TILE_R - 1) / TILE_R, CONV_THREADS, CONV_SMEM>>>(xf, mx, Wm1, bm1, xf, NF);
}

// round 6
// speedup vs baseline: 2.4326x; 1.0009x over previous
#include <cuda_runtime.h>

#define NV 100000
#define NE 200000
#define NF 100000
#define N_EV 400000
#define N_FE 800000
#define N_FF 800000
#define WD 128
#define NDST_TOT (NE + NF + NF)          // 400000 combined dst slots
#define NEDGE_TOT (N_EV + N_FE + N_FF)   // 2,000,000 combined edges

// Scratch (allocation-free rule: __device__ globals). x_f lives in d_out.
__device__ __align__(16) float g_xv[NV * WD];
__device__ __align__(16) float g_xe[NE * WD];
__device__ __align__(16) float g_max[NE * WD];
__device__ int g_cnt[NDST_TOT];
__device__ int g_ptr[NDST_TOT];
__device__ int g_cur[NDST_TOT];
__device__ int g_bsum[256];
__device__ int g_csr[NEDGE_TOT];
__device__ unsigned g_barcnt;
__device__ volatile unsigned g_bargen;

typedef unsigned long long u64;

__device__ __forceinline__ u64 pk2(float lo, float hi) {
    u64 r; asm("mov.b64 %0, {%1,%2};" : "=l"(r) : "f"(lo), "f"(hi)); return r;
}
__device__ __forceinline__ float2 upk2(u64 v) {
    float2 r; asm("mov.b64 {%0,%1}, %2;" : "=f"(r.x), "=f"(r.y) : "l"(v)); return r;
}
// Packed fp32x2 FMA: 2x the FFMA rate on sm_103a (PTX-only form).
__device__ __forceinline__ u64 ffma2(u64 a, u64 b, u64 c) {
    u64 d; asm("fma.rn.f32x2 %0, %1, %2, %3;" : "=l"(d) : "l"(a), "l"(b), "l"(c)); return d;
}
__device__ __forceinline__ void cp16(unsigned dst, const void* src, int srcsz) {
    asm volatile("cp.async.cg.shared.global [%0], [%1], 16, %2;"
                 :: "r"(dst), "l"(src), "r"(srcsz));
}
#define CP_COMMIT() asm volatile("cp.async.commit_group;")
#define CP_WAIT1()  asm volatile("cp.async.wait_group 1;")
#define CP_WAIT0()  asm volatile("cp.async.wait_group 0;")

// ---------------- software global barrier (all blocks co-resident) ----------------
__device__ __forceinline__ void gbar() {
    __syncthreads();
    if (threadIdx.x == 0) {
        unsigned gen = g_bargen;
        __threadfence();
        if (atomicAdd(&g_barcnt, 1) == gridDim.x - 1) {
            g_barcnt = 0;
            __threadfence();
            g_bargen = gen + 1;
        } else {
            while (g_bargen == gen) __nanosleep(64);
        }
        __threadfence();
    }
    __syncthreads();
}

// inclusive block scan (1024 threads), returns inclusive val; *tot = block total
__device__ __forceinline__ int block_scan_incl(int v, int* tot, int* swarp) {
    int lane = threadIdx.x & 31, wid = threadIdx.x >> 5;
    int s = v;
#pragma unroll
    for (int o = 1; o < 32; o <<= 1) { int t = __shfl_up_sync(~0u, s, o); if (lane >= o) s += t; }
    if (lane == 31) swarp[wid] = s;
    __syncthreads();
    if (wid == 0) {
        int w = swarp[lane];
#pragma unroll
        for (int o = 1; o < 32; o <<= 1) { int t = __shfl_up_sync(~0u, w, o); if (lane >= o) w += t; }
        swarp[lane] = w;
    }
    __syncthreads();
    int add = (wid > 0) ? swarp[wid - 1] : 0;
    *tot = swarp[31];
    int r = s + add;
    __syncthreads();
    return r;
}

// ---------------- build all 3 CSRs in ONE kernel ----------------
__global__ void __launch_bounds__(1024)
build_csr_all(const int* __restrict__ etv_v, const int* __restrict__ etv_e,
              const int* __restrict__ fte_e, const int* __restrict__ fte_f,
              const int* __restrict__ ftf_src, const int* __restrict__ ftf_dst)
{
    __shared__ int swarp[32];
    int gtid = blockIdx.x * 1024 + threadIdx.x;
    int gstride = gridDim.x * 1024;

    // zero counts
    for (int i = gtid; i < NDST_TOT; i += gstride) g_cnt[i] = 0;
    gbar();
    // histogram all 3 graphs
    for (int e = gtid; e < N_EV; e += gstride) atomicAdd(&g_cnt[__ldg(etv_e + e)], 1);
    for (int e = gtid; e < N_FE; e += gstride) atomicAdd(&g_cnt[NE + __ldg(fte_f + e)], 1);
    for (int e = gtid; e < N_FF; e += gstride) atomicAdd(&g_cnt[NE + NF + __ldg(ftf_dst + e)], 1);
    gbar();
    // exclusive scan over combined counts
    const int CHUNK = (NDST_TOT + gridDim.x - 1) / gridDim.x;
    int base = blockIdx.x * CHUNK;
    int lim = min(base + CHUNK, NDST_TOT);
    int carry = 0;
    for (int t = base; t < base + CHUNK; t += 1024) {
        int i = t + threadIdx.x;
        int v = (i < lim) ? g_cnt[i] : 0;
        int tot; int incl = block_scan_incl(v, &tot, swarp);
        if (i < lim) g_ptr[i] = carry + incl - v;
        carry += tot;
    }
    if (threadIdx.x == 0) g_bsum[blockIdx.x] = carry;
    gbar();
    if (blockIdx.x == 0) {
        int v = ((int)threadIdx.x < (int)gridDim.x) ? g_bsum[threadIdx.x] : 0;
        int tot; int incl = block_scan_incl(v, &tot, swarp);
        if ((int)threadIdx.x < (int)gridDim.x) g_bsum[threadIdx.x] = incl - v;
    }
    gbar();
    {
        int off = g_bsum[blockIdx.x];
        for (int i = base + threadIdx.x; i < lim; i += 1024) {
            int p = g_ptr[i] + off; g_ptr[i] = p; g_cur[i] = p;
        }
    }
    gbar();
    // fill CSR (order within a segment is irrelevant: consumer is min-reduce)
    for (int e = gtid; e < N_EV; e += gstride) {
        int d = __ldg(etv_e + e);
        g_csr[atomicAdd(&g_cur[d], 1)] = __ldg(etv_v + e);
    }
    for (int e = gtid; e < N_FE; e += gstride) {
        int d = NE + __ldg(fte_f + e);
        g_csr[atomicAdd(&g_cur[d], 1)] = __ldg(fte_e + e);
    }
    for (int e = gtid; e < N_FF; e += gstride) {
        int d = NE + NF + __ldg(ftf_dst + e);
        g_csr[atomicAdd(&g_cur[d], 1)] = __ldg(ftf_src + e);
    }
}

// ---------------- input embeddings: out = lrelu(in @ W + b) ----------------
template<int CIN>
__global__ void embed_kernel(const float* __restrict__ in, const float* __restrict__ Wt,
                             const float* __restrict__ bias, float* __restrict__ out, int n)
{
    __shared__ float sW[CIN * WD];
    __shared__ float sB[WD];
    for (int i = threadIdx.x; i < CIN * WD; i += blockDim.x) sW[i] = Wt[i];
    if (threadIdx.x < WD) sB[threadIdx.x] = bias[threadIdx.x];
    __syncthreads();
    int idx = blockIdx.x * blockDim.x + threadIdx.x;
    if (idx >= n * WD) return;
    int row = idx >> 7, j = idx & (WD - 1);
    float acc = sB[j];
#pragma unroll
    for (int k = 0; k < CIN; k++) acc = fmaf(__ldg(in + row * CIN + k), sW[k * WD + j], acc);
    out[idx] = acc > 0.f ? acc : 0.01f * acc;
}

// ---------------- segment min -> maxes ----------------
// max_e(xdst[d] - xsrc[s_e]) == xdst[d] - min_e(xsrc[s_e])  (fp-monotone, exact)
__global__ void segmin_kernel(const float* __restrict__ xsrc, const float* __restrict__ xdst,
                              const int* __restrict__ ptr, const int* __restrict__ cnt,
                              const int* __restrict__ csr, float* __restrict__ out, int ndst)
{
    int w = (blockIdx.x * blockDim.x + threadIdx.x) >> 5;
    if (w >= ndst) return;
    int lane = threadIdx.x & 31;
    int deg = __ldg(cnt + w);
    int base = __ldg(ptr + w);
    const float inf = __int_as_float(0x7f800000);
    float4 mn = make_float4(inf, inf, inf, inf);
    int i = 0;
    for (; i + 2 <= deg; i += 2) {
        int s0 = __ldg(csr + base + i), s1 = __ldg(csr + base + i + 1);
        float4 v0 = __ldg((const float4*)(xsrc + (size_t)s0 * WD) + lane);
        float4 v1 = __ldg((const float4*)(xsrc + (size_t)s1 * WD) + lane);
        mn.x = fminf(mn.x, fminf(v0.x, v1.x)); mn.y = fminf(mn.y, fminf(v0.y, v1.y));
        mn.z = fminf(mn.z, fminf(v0.z, v1.z)); mn.w = fminf(mn.w, fminf(v0.w, v1.w));
    }
    if (i < deg) {
        int s = __ldg(csr + base + i);
        float4 v = __ldg((const float4*)(xsrc + (size_t)s * WD) + lane);
        mn.x = fminf(mn.x, v.x); mn.y = fminf(mn.y, v.y);
        mn.z = fminf(mn.z, v.z); mn.w = fminf(mn.w, v.w);
    }
    float4 o;
    if (deg > 0) {
        float4 a = __ldg((const float4*)(xdst + (size_t)w * WD) + lane);
        o = make_float4(a.x - mn.x, a.y - mn.y, a.z - mn.z, a.w - mn.w);
    } else {
        o = make_float4(0.f, 0.f, 0.f, 0.f);
    }
    ((float4*)(out + (size_t)w * WD))[lane] = o;
}

// ---------------- conv GEMM: out = xdst + lrelu([xdst | maxes] @ Wm + bm) ----------------
// 256 threads, tile 128 rows x 128 cols, K=256 streamed as 4 x 64 chunks,
// double-buffered cp.async. Thread tile: 4 rows x 16 cols (8 f32x2 accs/row).
#define CONV_THREADS 256
#define TILE_R 128
#define KC 64
#define HSTR 68
#define CONV_SMEM ((256 * WD + WD + 2 * TILE_R * HSTR) * 4)   // 201216 B

__global__ void __launch_bounds__(CONV_THREADS, 1)
conv_kernel(const float* __restrict__ xdst, const float* __restrict__ maxbuf,
            const float* __restrict__ Wm, const float* __restrict__ bm,
            float* __restrict__ out, int n)
{
    extern __shared__ float smem[];
    float* sW = smem;                  // [256][128]
    float* sB = sW + 256 * WD;         // [128]
    float* sH = sB + WD;               // [2][TILE_R][HSTR]

    int tid = threadIdx.x;
    int row0 = blockIdx.x * TILE_R;
    int rg = tid >> 3;                 // 0..31 -> rows rg*4..rg*4+3
    int cgp = tid & 7;                 // col pairs cgp + 8*cc, cc=0..7

    unsigned sWa = (unsigned)__cvta_generic_to_shared(sW);
    unsigned sHa = (unsigned)__cvta_generic_to_shared(sH);

    // prologue: async-load W + h chunk 0 (group 0)
    {
        const char* wsrc = (const char*)Wm;
#pragma unroll 4
        for (int t = 0; t < 32; t++) {
            int w = tid + t * 256;
            cp16(sWa + w * 16, wsrc + w * 16, 16);
        }
    }
    // h chunk loader: chunk c covers k [c*64, c*64+64); c<2 from xdst, else maxbuf
    // 2048 16B words per chunk, 8 per thread
    {
        const char* src = (const char*)xdst;
#pragma unroll
        for (int t = 0; t < 8; t++) {
            int idx = tid + t * 256;
            int row = idx >> 4, w = idx & 15;
            int sz = (row0 + row < n) ? 16 : 0;
            cp16(sHa + (row * HSTR) * 4 + w * 16,
                 src + (size_t)(row0 + row) * 512 + w * 16, sz);
        }
    }
    CP_COMMIT();
    if (tid < WD) sB[tid] = bm[tid];

    const u64* sW2 = (const u64*)sW;
    u64 acc[4][8];

#pragma unroll 1
    for (int c = 0; c < 4; c++) {
        if (c + 1 < 4) {   // prefetch chunk c+1 into buf (c+1)&1
            int cn = c + 1;
            const char* src = (const char*)((cn < 2) ? xdst : maxbuf);
            int cboff = (cn & 1) * 256;
            unsigned hb = sHa + ((cn & 1) * TILE_R * HSTR) * 4;
#pragma unroll
            for (int t = 0; t < 8; t++) {
                int idx = tid + t * 256;
                int row = idx >> 4, w = idx & 15;
                int sz = (row0 + row < n) ? 16 : 0;
                cp16(hb + (row * HSTR) * 4 + w * 16,
                     src + (size_t)(row0 + row) * 512 + cboff + w * 16, sz);
            }
            CP_COMMIT();
            CP_WAIT1();
        } else {
            CP_WAIT0();
        }
        __syncthreads();

        if (c == 0) {
            const u64* sB2 = (const u64*)sB;
#pragma unroll
            for (int cc = 0; cc < 8; cc++) {
                u64 b2 = sB2[cgp + 8 * cc];
#pragma unroll
                for (int r = 0; r < 4; r++) acc[r][cc] = b2;
            }
        }

        const float* hb = sH + (c & 1) * TILE_R * HSTR + (rg * 4) * HSTR;
        int kbase = c * KC;
#pragma unroll 1
        for (int k4 = 0; k4 < KC / 4; k4++) {
            float4 h4[4];
#pragma unroll
            for (int r = 0; r < 4; r++) h4[r] = *(const float4*)(hb + r * HSTR + k4 * 4);
#pragma unroll
            for (int kk = 0; kk < 4; kk++) {
                const u64* wr = sW2 + (size_t)(kbase + k4 * 4 + kk) * 64 + cgp;
                u64 w[8];
#pragma unroll
                for (int cc = 0; cc < 8; cc++) w[cc] = wr[8 * cc];
#pragma unroll
                for (int r = 0; r < 4; r++) {
                    float hv = (kk == 0) ? h4[r].x : (kk == 1) ? h4[r].y
                             : (kk == 2) ? h4[r].z : h4[r].w;
                    u64 h2 = pk2(hv, hv);
#pragma unroll
                    for (int cc = 0; cc < 8; cc++) acc[r][cc] = ffma2(h2, w[cc], acc[r][cc]);
                }
            }
        }
        __syncthreads();
    }

    // epilogue: lrelu into smem stage, then coalesced residual+store
    float* sO = sH;   // [TILE_R][132], 16896 floats <= 17408 available
#pragma unroll
    for (int r = 0; r < 4; r++) {
        int lrow = rg * 4 + r;
#pragma unroll
        for (int cc = 0; cc < 8; cc++) {
            float2 v = upk2(acc[r][cc]);
            float2 a;
            a.x = v.x > 0.f ? v.x : 0.01f * v.x;
            a.y = v.y > 0.f ? v.y : 0.01f * v.y;
            *(float2*)(sO + lrow * 132 + 2 * (cgp + 8 * cc)) = a;
        }
    }
    __syncthreads();
#pragma unroll 1
    for (int idx = tid; idx < TILE_R * 32; idx += CONV_THREADS) {
        int row = idx >> 5, c4 = idx & 31;
        int grow = row0 + row;
        if (grow < n) {
            float4 o = *(const float4*)(sO + row * 132 + c4 * 4);
            float4 x = __ldg((const float4*)(xdst + (size_t)grow * WD) + c4);
            float4 res = make_float4(x.x + o.x, x.y + o.y, x.z + o.z, x.w + o.w);
            *((float4*)(out + (size_t)grow * WD) + c4) = res;
        }
    }
}

// ---------------- launch ----------------
extern "C" void kernel_launch(void* const* d_in, const int* in_sizes, int n_in,
                              void* d_out, int out_size)
{
    const float* vertices = (const float*)d_in[0];
    const float* edges    = (const float*)d_in[1];
    const float* faces    = (const float*)d_in[2];
    const int* etv_v   = (const int*)d_in[3];
    const int* etv_e   = (const int*)d_in[4];
    const int* fte_e   = (const int*)d_in[5];
    const int* fte_f   = (const int*)d_in[6];
    const int* ftf_src = (const int*)d_in[7];
    const int* ftf_dst = (const int*)d_in[8];
    const float* Wv   = (const float*)d_in[9];
    const float* bv   = (const float*)d_in[10];
    const float* We   = (const float*)d_in[11];
    const float* be   = (const float*)d_in[12];
    const float* Wf   = (const float*)d_in[13];
    const float* bf   = (const float*)d_in[14];
    const float* Wv2e = (const float*)d_in[15];
    const float* bv2e = (const float*)d_in[16];
    const float* We2f = (const float*)d_in[17];
    const float* be2f = (const float*)d_in[18];
    const float* Wm0  = (const float*)d_in[19];
    const float* bm0  = (const float*)d_in[20];
    const float* Wm1  = (const float*)d_in[21];
    const float* bm1  = (const float*)d_in[22];

    float *xv, *xe, *mx;
    int *cnt, *ptr, *csr;
    cudaGetSymbolAddress((void**)&xv, g_xv);
    cudaGetSymbolAddress((void**)&xe, g_xe);
    cudaGetSymbolAddress((void**)&mx, g_max);
    cudaGetSymbolAddress((void**)&cnt, g_cnt);
    cudaGetSymbolAddress((void**)&ptr, g_ptr);
    cudaGetSymbolAddress((void**)&csr, g_csr);
    float* xf = (float*)d_out;

    cudaFuncSetAttribute(conv_kernel, cudaFuncAttributeMaxDynamicSharedMemorySize, CONV_SMEM);

    // launch 0: all 3 CSRs (index-only; independent of features)
    build_csr_all<<<148, 1024>>>(etv_v, etv_e, fte_e, fte_f, ftf_src, ftf_dst);

    // launches 1-3: embeddings
    embed_kernel<3><<<(NV * WD + 255) / 256, 256>>>(vertices, Wv, bv, xv, NV);
    embed_kernel<12><<<(NE * WD + 255) / 256, 256>>>(edges, We, be, xe, NE);
    embed_kernel<14><<<(NF * WD + 255) / 256, 256>>>(faces, Wf, bf, xf, NF);

    // V2E (launches 4,5 — conv1 is the ncu-profiled launch)
    segmin_kernel<<<(NE + 7) / 8, 256>>>(xv, xe, ptr, cnt, csr, mx, NE);
    conv_kernel<<<(NE + TILE_R - 1) / TILE_R, CONV_THREADS, CONV_SMEM>>>(xe, mx, Wv2e, bv2e, xe, NE);

    // E2F
    segmin_kernel<<<(NF + 7) / 8, 256>>>(xe, xf, ptr + NE, cnt + NE, csr, mx, NF);
    conv_kernel<<<(NF + TILE_R - 1) / TILE_R, CONV_THREADS, CONV_SMEM>>>(xf, mx, We2f, be2f, xf, NF);

    // FF message layer 0 (ftf CSR reused)
    segmin_kernel<<<(NF + 7) / 8, 256>>>(xf, xf, ptr + NE + NF, cnt + NE + NF, csr, mx, NF);
    conv_kernel<<<(NF + TILE_R - 1) / TILE_R, CONV_THREADS, CONV_SMEM>>>(xf, mx, Wm0, bm0, xf, NF);

    // FF message layer 1
    segmin_kernel<<<(NF + 7) / 8, 256>>>(xf, xf, ptr + NE + NF, cnt + NE + NF, csr, mx, NF);
    conv_kernel<<<(NF + TILE_R - 1) / TILE_R, CONV_THREADS, CONV_SMEM>>>(xf, mx, Wm1, bm1, xf, NF);
}

// round 9
// speedup vs baseline: 2.7582x; 1.1338x over previous
#include <cuda_runtime.h>

#define NV 100000
#define NE 200000
#define NF 100000
#define N_EV 400000
#define N_FE 800000
#define N_FF 800000
#define WD 128
#define NDST_TOT (NE + NF + NF)
#define NEDGE_TOT (N_EV + N_FE + N_FF)

__device__ __align__(16) float g_xv[NV * WD];
__device__ __align__(16) float g_xe[NE * WD];
__device__ __align__(16) float g_max[NE * WD];
__device__ int g_cnt[NDST_TOT];
__device__ int g_ptr[NDST_TOT];
__device__ int g_cur[NDST_TOT];
__device__ int g_bsum[256];
__device__ int g_csr[NEDGE_TOT];
__device__ unsigned g_barcnt;
__device__ volatile unsigned g_bargen;

typedef unsigned long long u64;

__device__ __forceinline__ u64 pk2(float lo, float hi) {
    u64 r; asm("mov.b64 %0, {%1,%2};" : "=l"(r) : "f"(lo), "f"(hi)); return r;
}
__device__ __forceinline__ float2 upk2(u64 v) {
    float2 r; asm("mov.b64 {%0,%1}, %2;" : "=f"(r.x), "=f"(r.y) : "l"(v)); return r;
}
// Packed fp32x2 FMA: 2x FFMA rate on sm_103a (PTX-only form).
__device__ __forceinline__ u64 ffma2(u64 a, u64 b, u64 c) {
    u64 d; asm("fma.rn.f32x2 %0, %1, %2, %3;" : "=l"(d) : "l"(a), "l"(b), "l"(c)); return d;
}
__device__ __forceinline__ void cp16(unsigned dst, const void* src, int srcsz) {
    asm volatile("cp.async.cg.shared.global [%0], [%1], 16, %2;"
                 :: "r"(dst), "l"(src), "r"(srcsz));
}
#define CP_COMMIT() asm volatile("cp.async.commit_group;")
#define CP_WAIT1()  asm volatile("cp.async.wait_group 1;")
#define CP_WAIT0()  asm volatile("cp.async.wait_group 0;")

// ---------------- software global barrier (all blocks co-resident) ----------------
__device__ __forceinline__ void gbar() {
    __syncthreads();
    if (threadIdx.x == 0) {
        unsigned gen = g_bargen;
        __threadfence();
        if (atomicAdd(&g_barcnt, 1) == gridDim.x - 1) {
            g_barcnt = 0; __threadfence(); g_bargen = gen + 1;
        } else { while (g_bargen == gen) __nanosleep(64); }
        __threadfence();
    }
    __syncthreads();
}

__device__ __forceinline__ int block_scan_incl(int v, int* tot, int* swarp) {
    int lane = threadIdx.x & 31, wid = threadIdx.x >> 5;
    int s = v;
#pragma unroll
    for (int o = 1; o < 32; o <<= 1) { int t = __shfl_up_sync(~0u, s, o); if (lane >= o) s += t; }
    if (lane == 31) swarp[wid] = s;
    __syncthreads();
    if (wid == 0) {
        int w = swarp[lane];
#pragma unroll
        for (int o = 1; o < 32; o <<= 1) { int t = __shfl_up_sync(~0u, w, o); if (lane >= o) w += t; }
        swarp[lane] = w;
    }
    __syncthreads();
    int add = (wid > 0) ? swarp[wid - 1] : 0;
    *tot = swarp[31];
    int r = s + add;
    __syncthreads();
    return r;
}

// ---------------- build all 3 CSRs in ONE kernel ----------------
__global__ void __launch_bounds__(1024)
build_csr_all(const int* __restrict__ etv_v, const int* __restrict__ etv_e,
              const int* __restrict__ fte_e, const int* __restrict__ fte_f,
              const int* __restrict__ ftf_src, const int* __restrict__ ftf_dst)
{
    __shared__ int swarp[32];
    int gtid = blockIdx.x * 1024 + threadIdx.x, gs = gridDim.x * 1024;
    for (int i = gtid; i < NDST_TOT; i += gs) g_cnt[i] = 0;
    gbar();
    for (int e = gtid; e < N_EV; e += gs) atomicAdd(&g_cnt[__ldg(etv_e + e)], 1);
    for (int e = gtid; e < N_FE; e += gs) atomicAdd(&g_cnt[NE + __ldg(fte_f + e)], 1);
    for (int e = gtid; e < N_FF; e += gs) atomicAdd(&g_cnt[NE + NF + __ldg(ftf_dst + e)], 1);
    gbar();
    const int CHUNK = (NDST_TOT + gridDim.x - 1) / gridDim.x;
    int base = blockIdx.x * CHUNK, lim = min(base + CHUNK, NDST_TOT), carry = 0;
    for (int t = base; t < base + CHUNK; t += 1024) {
        int i = t + threadIdx.x;
        int v = (i < lim) ? g_cnt[i] : 0;
        int tot; int incl = block_scan_incl(v, &tot, swarp);
        if (i < lim) g_ptr[i] = carry + incl - v;
        carry += tot;
    }
    if (threadIdx.x == 0) g_bsum[blockIdx.x] = carry;
    gbar();
    if (blockIdx.x == 0) {
        int v = ((int)threadIdx.x < (int)gridDim.x) ? g_bsum[threadIdx.x] : 0;
        int tot; int incl = block_scan_incl(v, &tot, swarp);
        if ((int)threadIdx.x < (int)gridDim.x) g_bsum[threadIdx.x] = incl - v;
    }
    gbar();
    {
        int off = g_bsum[blockIdx.x];
        for (int i = base + threadIdx.x; i < lim; i += 1024) {
            int p = g_ptr[i] + off; g_ptr[i] = p; g_cur[i] = p;
        }
    }
    gbar();
    for (int e = gtid; e < N_EV; e += gs) {
        int d = __ldg(etv_e + e);
        g_csr[atomicAdd(&g_cur[d], 1)] = __ldg(etv_v + e);
    }
    for (int e = gtid; e < N_FE; e += gs) {
        int d = NE + __ldg(fte_f + e);
        g_csr[atomicAdd(&g_cur[d], 1)] = __ldg(fte_e + e);
    }
    for (int e = gtid; e < N_FF; e += gs) {
        int d = NE + NF + __ldg(ftf_dst + e);
        g_csr[atomicAdd(&g_cur[d], 1)] = __ldg(ftf_src + e);
    }
}

// ---------------- embeddings: warp per row, shfl-broadcast inputs ----------------
template<int CIN>
__global__ void embed2_kernel(const float* __restrict__ in, const float* __restrict__ Wt,
                              const float* __restrict__ bias, float* __restrict__ out, int n)
{
    __shared__ u64 sW2[CIN * 64];
    __shared__ u64 sB2[64];
    for (int i = threadIdx.x; i < CIN * 64; i += 256) sW2[i] = *(const u64*)(Wt + 2 * i);
    if (threadIdx.x < 64) sB2[threadIdx.x] = *(const u64*)(bias + 2 * threadIdx.x);
    __syncthreads();
    int w = blockIdx.x * 8 + (threadIdx.x >> 5);
    if (w >= n) return;
    int lane = threadIdx.x & 31;
    float xv = (lane < CIN) ? __ldg(in + (size_t)w * CIN + lane) : 0.f;
    u64 a0 = sB2[2 * lane], a1 = sB2[2 * lane + 1];
#pragma unroll
    for (int k = 0; k < CIN; k++) {
        float xk = __shfl_sync(~0u, xv, k);
        u64 h2 = pk2(xk, xk);
        a0 = ffma2(h2, sW2[k * 64 + 2 * lane], a0);
        a1 = ffma2(h2, sW2[k * 64 + 2 * lane + 1], a1);
    }
    float2 v0 = upk2(a0), v1 = upk2(a1);
    float4 r;
    r.x = v0.x > 0.f ? v0.x : 0.01f * v0.x;
    r.y = v0.y > 0.f ? v0.y : 0.01f * v0.y;
    r.z = v1.x > 0.f ? v1.x : 0.01f * v1.x;
    r.w = v1.y > 0.f ? v1.y : 0.01f * v1.y;
    *(float4*)(out + (size_t)w * WD + lane * 4) = r;
}

// ---------------- segment min -> maxes (fp-exact transform of segment-max-of-diff) ----------------
__global__ void segmin_kernel(const float* __restrict__ xsrc, const float* __restrict__ xdst,
                              const int* __restrict__ ptr, const int* __restrict__ cnt,
                              const int* __restrict__ csr, float* __restrict__ out, int ndst)
{
    int w = (blockIdx.x * blockDim.x + threadIdx.x) >> 5;
    if (w >= ndst) return;
    int lane = threadIdx.x & 31;
    int deg = __ldg(cnt + w), base = __ldg(ptr + w);
    const float inf = __int_as_float(0x7f800000);
    float4 mn = make_float4(inf, inf, inf, inf);
    int i = 0;
    for (; i + 2 <= deg; i += 2) {
        int s0 = __ldg(csr + base + i), s1 = __ldg(csr + base + i + 1);
        float4 v0 = __ldg((const float4*)(xsrc + (size_t)s0 * WD) + lane);
        float4 v1 = __ldg((const float4*)(xsrc + (size_t)s1 * WD) + lane);
        mn.x = fminf(mn.x, fminf(v0.x, v1.x)); mn.y = fminf(mn.y, fminf(v0.y, v1.y));
        mn.z = fminf(mn.z, fminf(v0.z, v1.z)); mn.w = fminf(mn.w, fminf(v0.w, v1.w));
    }
    if (i < deg) {
        int s = __ldg(csr + base + i);
        float4 v = __ldg((const float4*)(xsrc + (size_t)s * WD) + lane);
        mn.x = fminf(mn.x, v.x); mn.y = fminf(mn.y, v.y);
        mn.z = fminf(mn.z, v.z); mn.w = fminf(mn.w, v.w);
    }
    float4 o = make_float4(0.f, 0.f, 0.f, 0.f);
    if (deg > 0) {
        float4 a = __ldg((const float4*)(xdst + (size_t)w * WD) + lane);
        o = make_float4(a.x - mn.x, a.y - mn.y, a.z - mn.z, a.w - mn.w);
    }
    ((float4*)(out + (size_t)w * WD))[lane] = o;
}

// ---------------- conv GEMM: out = xdst + lrelu([xdst | maxes] @ Wm + bm) ----------------
// 256 threads, tile 128 rows x 128 cols, K=256 in 4 x 64 chunks.
// BOTH W (32KB/chunk) and h (34KB/chunk) double-buffered via cp.async.
#define CONV_THREADS 256
#define TILE_R 128
#define KC 64
#define HSTR 68
#define WCH (KC * WD)                                   // floats per W chunk (8192)
#define CONV_SMEM ((2 * WCH + WD + 2 * TILE_R * HSTR) * 4)   // 135680 B

__global__ void __launch_bounds__(CONV_THREADS, 1)
conv_kernel(const float* __restrict__ xdst, const float* __restrict__ maxbuf,
            const float* __restrict__ Wm, const float* __restrict__ bm,
            float* __restrict__ out, int n)
{
    extern __shared__ float smem[];
    float* sW = smem;                   // [2][KC][128]
    float* sB = sW + 2 * WCH;           // [128]
    float* sH = sB + WD;                // [2][TILE_R][HSTR]

    int tid = threadIdx.x;
    int row0 = blockIdx.x * TILE_R;
    int rg = tid >> 3;                  // 0..31 -> rows rg*4..rg*4+3
    int cgp = tid & 7;                  // col pairs cgp + 8*cc, cc=0..7

    unsigned sWa = (unsigned)__cvta_generic_to_shared(sW);
    unsigned sHa = (unsigned)__cvta_generic_to_shared(sH);

    // prologue: W chunk 0 + h chunk 0 (one group)
    {
        const char* wsrc = (const char*)Wm;
#pragma unroll
        for (int t = 0; t < 8; t++) {
            int u = tid + t * 256;                      // 2048 16B units
            cp16(sWa + u * 16, wsrc + u * 16, 16);
        }
        const char* src = (const char*)xdst;
#pragma unroll
        for (int t = 0; t < 8; t++) {
            int idx = tid + t * 256;
            int row = idx >> 4, u = idx & 15;
            int sz = (row0 + row < n) ? 16 : 0;
            cp16(sHa + (row * HSTR) * 4 + u * 16,
                 src + (size_t)(row0 + row) * 512 + u * 16, sz);
        }
    }
    CP_COMMIT();
    if (tid < WD) sB[tid] = bm[tid];

    u64 acc[4][8];

#pragma unroll 1
    for (int c = 0; c < 4; c++) {
        if (c + 1 < 4) {    // prefetch W+h chunk c+1 into buffers (c+1)&1
            int cn = c + 1;
            const char* wsrc = (const char*)Wm + (size_t)cn * WCH * 4;
            unsigned wb = sWa + ((cn & 1) * WCH) * 4;
#pragma unroll
            for (int t = 0; t < 8; t++) {
                int u = tid + t * 256;
                cp16(wb + u * 16, wsrc + u * 16, 16);
            }
            const char* src = (const char*)((cn < 2) ? xdst : maxbuf);
            int cboff = (cn & 1) * 256;
            unsigned hb = sHa + ((cn & 1) * TILE_R * HSTR) * 4;
#pragma unroll
            for (int t = 0; t < 8; t++) {
                int idx = tid + t * 256;
                int row = idx >> 4, u = idx & 15;
                int sz = (row0 + row < n) ? 16 : 0;
                cp16(hb + (row * HSTR) * 4 + u * 16,
                     src + (size_t)(row0 + row) * 512 + cboff + u * 16, sz);
            }
            CP_COMMIT();
            CP_WAIT1();
        } else {
            CP_WAIT0();
        }
        __syncthreads();

        if (c == 0) {
            const u64* sB2 = (const u64*)sB;
#pragma unroll
            for (int cc = 0; cc < 8; cc++) {
                u64 b2 = sB2[cgp + 8 * cc];
#pragma unroll
                for (int r = 0; r < 4; r++) acc[r][cc] = b2;
            }
        }

        const u64* sWc = (const u64*)(sW + (c & 1) * WCH);   // [64][64 pairs]
        const float* hb = sH + (c & 1) * TILE_R * HSTR + (rg * 4) * HSTR;
#pragma unroll 1
        for (int k4 = 0; k4 < KC / 4; k4++) {
            float4 h4[4];
#pragma unroll
            for (int r = 0; r < 4; r++) h4[r] = *(const float4*)(hb + r * HSTR + k4 * 4);
#pragma unroll
            for (int kk = 0; kk < 4; kk++) {
                const u64* wr = sWc + (k4 * 4 + kk) * 64 + cgp;
                u64 w[8];
#pragma unroll
                for (int cc = 0; cc < 8; cc++) w[cc] = wr[8 * cc];
#pragma unroll
                for (int r = 0; r < 4; r++) {
                    float hv = (kk == 0) ? h4[r].x : (kk == 1) ? h4[r].y
                             : (kk == 2) ? h4[r].z : h4[r].w;
                    u64 h2 = pk2(hv, hv);
#pragma unroll
                    for (int cc = 0; cc < 8; cc++) acc[r][cc] = ffma2(h2, w[cc], acc[r][cc]);
                }
            }
        }
        __syncthreads();
    }

    // epilogue: lrelu into smem stage, then coalesced residual+store
    float* sO = sH;   // [TILE_R][132] = 16896 floats <= 17408
#pragma unroll
    for (int r = 0; r < 4; r++) {
        int lrow = rg * 4 + r;
#pragma unroll
        for (int cc = 0; cc < 8; cc++) {
            float2 v = upk2(acc[r][cc]);
            float2 a;
            a.x = v.x > 0.f ? v.x : 0.01f * v.x;
            a.y = v.y > 0.f ? v.y : 0.01f * v.y;
            *(float2*)(sO + lrow * 132 + 2 * (cgp + 8 * cc)) = a;
        }
    }
    __syncthreads();
#pragma unroll 1
    for (int idx = tid; idx < TILE_R * 32; idx += CONV_THREADS) {
        int row = idx >> 5, c4 = idx & 31;
        int grow = row0 + row;
        if (grow < n) {
            float4 o = *(const float4*)(sO + row * 132 + c4 * 4);
            float4 x = __ldg((const float4*)(xdst + (size_t)grow * WD) + c4);
            float4 res = make_float4(x.x + o.x, x.y + o.y, x.z + o.z, x.w + o.w);
            *((float4*)(out + (size_t)grow * WD) + c4) = res;
        }
    }
}

// ---------------- launch ----------------
extern "C" void kernel_launch(void* const* d_in, const int* in_sizes, int n_in,
                              void* d_out, int out_size)
{
    const float* vertices = (const float*)d_in[0];
    const float* edges    = (const float*)d_in[1];
    const float* faces    = (const float*)d_in[2];
    const int* etv_v   = (const int*)d_in[3];
    const int* etv_e   = (const int*)d_in[4];
    const int* fte_e   = (const int*)d_in[5];
    const int* fte_f   = (const int*)d_in[6];
    const int* ftf_src = (const int*)d_in[7];
    const int* ftf_dst = (const int*)d_in[8];
    const float* Wv   = (const float*)d_in[9];
    const float* bv   = (const float*)d_in[10];
    const float* We   = (const float*)d_in[11];
    const float* be   = (const float*)d_in[12];
    const float* Wf   = (const float*)d_in[13];
    const float* bf   = (const float*)d_in[14];
    const float* Wv2e = (const float*)d_in[15];
    const float* bv2e = (const float*)d_in[16];
    const float* We2f = (const float*)d_in[17];
    const float* be2f = (const float*)d_in[18];
    const float* Wm0  = (const float*)d_in[19];
    const float* bm0  = (const float*)d_in[20];
    const float* Wm1  = (const float*)d_in[21];
    const float* bm1  = (const float*)d_in[22];

    float *xv, *xe, *mx;
    int *cnt, *ptr, *csr;
    cudaGetSymbolAddress((void**)&xv, g_xv);
    cudaGetSymbolAddress((void**)&xe, g_xe);
    cudaGetSymbolAddress((void**)&mx, g_max);
    cudaGetSymbolAddress((void**)&cnt, g_cnt);
    cudaGetSymbolAddress((void**)&ptr, g_ptr);
    cudaGetSymbolAddress((void**)&csr, g_csr);
    float* xf = (float*)d_out;

    cudaFuncSetAttribute(conv_kernel, cudaFuncAttributeMaxDynamicSharedMemorySize, CONV_SMEM);

    // 0: all 3 CSRs (index-only)
    build_csr_all<<<148, 1024>>>(etv_v, etv_e, fte_e, fte_f, ftf_src, ftf_dst);

    // 1-3: embeddings (warp-per-row, no L1 replay)
    embed2_kernel<3><<<(NV + 7) / 8, 256>>>(vertices, Wv, bv, xv, NV);
    embed2_kernel<12><<<(NE + 7) / 8, 256>>>(edges, We, be, xe, NE);
    embed2_kernel<14><<<(NF + 7) / 8, 256>>>(faces, Wf, bf, xf, NF);

    // 4,5: V2E — launch index 5 is the ncu-profiled launch (big conv)
    segmin_kernel<<<(NE + 7) / 8, 256>>>(xv, xe, ptr, cnt, csr, mx, NE);
    conv_kernel<<<(NE + TILE_R - 1) / TILE_R, CONV_THREADS, CONV_SMEM>>>(xe, mx, Wv2e, bv2e, xe, NE);

    // E2F
    segmin_kernel<<<(NF + 7) / 8, 256>>>(xe, xf, ptr + NE, cnt + NE, csr, mx, NF);
    conv_kernel<<<(NF + TILE_R - 1) / TILE_R, CONV_THREADS, CONV_SMEM>>>(xf, mx, We2f, be2f, xf, NF);

    // FF layer 0 (ftf CSR reused)
    segmin_kernel<<<(NF + 7) / 8, 256>>>(xf, xf, ptr + NE + NF, cnt + NE + NF, csr, mx, NF);
    conv_kernel<<<(NF + TILE_R - 1) / TILE_R, CONV_THREADS, CONV_SMEM>>>(xf, mx, Wm0, bm0, xf, NF);

    // FF layer 1
    segmin_kernel<<<(NF + 7) / 8, 256>>>(xf, xf, ptr + NE + NF, cnt + NE + NF, csr, mx, NF);
    conv_kernel<<<(NF + TILE_R - 1) / TILE_R, CONV_THREADS, CONV_SMEM>>>(xf, mx, Wm1, bm1, xf, NF);
}